// round 5
// baseline (speedup 1.0000x reference)
#include <cuda_runtime.h>

// IntensityTransform: out[b,h,w,c] = it[b, clip(round(255*im[b,h,w,c]),0,255), c]
// im: [16,512,512,3] f32, it: [16,256,3] f32, out: [16,512,512,3] f32
//
// Latency-bound streaming gather. float4 vectorized; 8x bank-privatized LUT in
// smem; EXACT single wave (1184 blocks = 148 SM x 8) at 100% theoretical
// occupancy (launch_bounds caps regs at 32); __stcs output stores.

#define B_DIM 16
#define HWC   (512 * 512 * 3)                    // 786432 elements per batch
#define NVEC  (HWC / 4)                          // 196608 float4 per batch
#define THREADS 256
#define BLOCKS_PER_B 74                          // 74*16 = 1184 = 148 SMs * 8
#define STRIDE (THREADS * BLOCKS_PER_B)          // 18944  (== 2 mod 3)
#define MAX_ITERS 11                             // ceil(196608 / 18944)
#define REP 8                                    // LUT replication factor

__global__ __launch_bounds__(THREADS, 8)
void intensity_transform_kernel(const float* __restrict__ im,
                                const float* __restrict__ it,
                                float* __restrict__ out)
{
    // 768 LUT entries x 8 replicas = 24 KB. Entry e, replica r at [e*8 + r].
    // bank = 8*(e&3) + r  -> lanes only conflict within their own 4-lane
    // replica group, and only when e == e' (mod 4): E[max] ~2.2 vs ~3.3 bare.
    __shared__ float lut[768 * REP];

    const int b = blockIdx.y;

    // Stage replicated LUT: 768 entries / 256 threads = 3 per thread,
    // each broadcast-written as two float4 (32B-aligned: e*8 floats = 32B*e).
    {
        const float* it_b = it + (size_t)b * (256 * 3);
        #pragma unroll
        for (int k = 0; k < 3; k++) {
            int e = threadIdx.x + k * THREADS;
            float v = it_b[e];
            float4 vv = make_float4(v, v, v, v);
            *reinterpret_cast<float4*>(&lut[e * REP])     = vv;
            *reinterpret_cast<float4*>(&lut[e * REP + 4]) = vv;
        }
    }
    __syncthreads();

    const int r = (threadIdx.x >> 2) & (REP - 1);   // replica for this lane

    const float4* __restrict__ imv  = (const float4*)(im  + (size_t)b * HWC);
    float4*       __restrict__ outv = (float4*)      (out + (size_t)b * HWC);

    const int tid0 = blockIdx.x * THREADS + threadIdx.x;

    // channel of lane 0 of float4 j: (4*j) % 3 == j % 3.
    // STRIDE == 2 (mod 3)  ->  channels rotate (c0,c1,c2) <- (c2,c0,c1) per
    // iteration; free register renaming in the unrolled loop.
    int c0 = tid0 % 3;
    int c1 = c0 + 1; if (c1 == 3) c1 = 0;
    int c2 = c1 + 1; if (c2 == 3) c2 = 0;
    // lane 3 channel == c0

    int j = tid0;
    #pragma unroll
    for (int k = 0; k < MAX_ITERS; k++) {
        if (j < NVEC) {
            float4 v = imv[j];

            // round-half-to-even matches jnp.round exactly
            int i0 = __float2int_rn(255.0f * v.x);
            int i1 = __float2int_rn(255.0f * v.y);
            int i2 = __float2int_rn(255.0f * v.z);
            int i3 = __float2int_rn(255.0f * v.w);

            i0 = min(max(i0, 0), 255);
            i1 = min(max(i1, 0), 255);
            i2 = min(max(i2, 0), 255);
            i3 = min(max(i3, 0), 255);

            float4 o;
            o.x = lut[((i0 * 3 + c0) << 3) + r];
            o.y = lut[((i1 * 3 + c1) << 3) + r];
            o.z = lut[((i2 * 3 + c2) << 3) + r];
            o.w = lut[((i3 * 3 + c0) << 3) + r];

            // streaming store: don't let output evict the L2-resident input
            __stcs(&outv[j], o);
        }
        j += STRIDE;
        // rotate channel triple: new c0 = old c0 + 2 (mod 3)
        int t = c2; c2 = c1; c1 = c0; c0 = t;
    }
}

extern "C" void kernel_launch(void* const* d_in, const int* in_sizes, int n_in,
                              void* d_out, int out_size)
{
    const float* im = (const float*)d_in[0];   // [16,512,512,3]
    const float* it = (const float*)d_in[1];   // [16,256,3]
    float* out = (float*)d_out;

    dim3 grid(BLOCKS_PER_B, B_DIM);
    intensity_transform_kernel<<<grid, THREADS>>>(im, it, out);
}

// round 7
// speedup vs baseline: 1.0554x; 1.0554x over previous
#include <cuda_runtime.h>

// IntensityTransform: out[b,h,w,c] = it[b, clip(round(255*im[b,h,w,c]),0,255), c]
// im: [16,512,512,3] f32, it: [16,256,3] f32, out: [16,512,512,3] f32
//
// L1-wavefront-bound streaming gather. float4 vectorized; 16x bank-privatized
// LUT in smem (per-lane-pair private banks -> LDS replay ~2 deterministic);
// exact single wave at 4 blocks/SM with prefetch ILP (reg headroom is free
// at this occupancy); __stcs output stores.

#define B_DIM 16
#define HWC   (512 * 512 * 3)                    // 786432 elements per batch
#define NVEC  (HWC / 4)                          // 196608 float4 per batch
#define THREADS 256
#define BLOCKS_PER_B 37                          // 37*16 = 592 = 148 SMs * 4
#define STRIDE (THREADS * BLOCKS_PER_B)          // 9472  (== 1 mod 3)
#define MAX_ITERS 21                             // ceil(196608 / 9472)
#define REP 16                                   // LUT replication factor

__global__ __launch_bounds__(THREADS, 4)
void intensity_transform_kernel(const float* __restrict__ im,
                                const float* __restrict__ it,
                                float* __restrict__ out)
{
    // 768 LUT entries x 16 replicas = 48 KB. Entry e, replica r at [e*16 + r].
    // bank = 16*(e&1) + r : lane pair (2k,2k+1) owns replica r=k and banks
    // {k, k+16} exclusively -> per-bank load <= 2, warp replay <= 2 always.
    __shared__ float lut[768 * REP];

    const int b = blockIdx.y;

    // Stage replicated LUT: 768 entries / 256 threads = 3 per thread,
    // each broadcast-written as four float4 (e*16 floats = 64B-aligned).
    {
        const float* it_b = it + (size_t)b * (256 * 3);
        #pragma unroll
        for (int k = 0; k < 3; k++) {
            int e = threadIdx.x + k * THREADS;
            float v = it_b[e];
            float4 vv = make_float4(v, v, v, v);
            float4* dst = reinterpret_cast<float4*>(&lut[e * REP]);
            dst[0] = vv; dst[1] = vv; dst[2] = vv; dst[3] = vv;
        }
    }
    __syncthreads();

    const int r = (threadIdx.x >> 1) & (REP - 1);   // replica for this lane

    const float4* __restrict__ imv  = (const float4*)(im  + (size_t)b * HWC);
    float4*       __restrict__ outv = (float4*)      (out + (size_t)b * HWC);

    const int tid0 = blockIdx.x * THREADS + threadIdx.x;

    // channel of lane 0 of float4 j: (4*j) % 3 == j % 3.
    // STRIDE == 1 (mod 3) -> channels rotate (c0,c1,c2) <- (c1,c2,c0) per
    // iteration; free register renaming in the unrolled loop.
    int c0 = tid0 % 3;
    int c1 = c0 + 1; if (c1 == 3) c1 = 0;
    int c2 = c1 + 1; if (c2 == 3) c2 = 0;
    // lane 3 channel == c0

    // Software pipeline: one LDG in flight while doing LDS gathers.
    // Reg headroom at 4 blocks/SM is 64/thread, so this costs no occupancy.
    int j = tid0;
    float4 v = imv[j];   // tid0 < NVEC always (9472*1 <= 196608)

    #pragma unroll
    for (int k = 0; k < MAX_ITERS; k++) {
        const int jn = j + STRIDE;
        float4 vn;
        if (k + 1 < MAX_ITERS && jn < NVEC) vn = imv[jn];

        if (j < NVEC) {
            // round-half-to-even matches jnp.round exactly
            int i0 = __float2int_rn(255.0f * v.x);
            int i1 = __float2int_rn(255.0f * v.y);
            int i2 = __float2int_rn(255.0f * v.z);
            int i3 = __float2int_rn(255.0f * v.w);

            i0 = min(max(i0, 0), 255);
            i1 = min(max(i1, 0), 255);
            i2 = min(max(i2, 0), 255);
            i3 = min(max(i3, 0), 255);

            float4 o;
            o.x = lut[((i0 * 3 + c0) << 4) + r];
            o.y = lut[((i1 * 3 + c1) << 4) + r];
            o.z = lut[((i2 * 3 + c2) << 4) + r];
            o.w = lut[((i3 * 3 + c0) << 4) + r];

            // streaming store: don't let output evict the L2-resident input
            __stcs(&outv[j], o);
        }

        j = jn;
        v = vn;
        // rotate channel triple: new c0 = old c0 + 1 (mod 3)
        int t = c0; c0 = c1; c1 = c2; c2 = t;
    }
}

extern "C" void kernel_launch(void* const* d_in, const int* in_sizes, int n_in,
                              void* d_out, int out_size)
{
    const float* im = (const float*)d_in[0];   // [16,512,512,3]
    const float* it = (const float*)d_in[1];   // [16,256,3]
    float* out = (float*)d_out;

    dim3 grid(BLOCKS_PER_B, B_DIM);
    intensity_transform_kernel<<<grid, THREADS>>>(im, it, out);
}